// round 1
// baseline (speedup 1.0000x reference)
#include <cuda_runtime.h>
#include <math.h>

#define B 4
#define M 2048
#define DMODEL 512
#define NHEAD 8
#define DHEAD 64
#define NTOK (B*M)          // 8192
#define BH (B*NHEAD)        // 32

// ---------------- scratch (device globals; no runtime alloc allowed) ----------------
__device__ float g_q[BH * M * DHEAD];    // [b,h,m,dh]
__device__ float g_k[BH * M * DHEAD];
__device__ float g_v[BH * M * DHEAD];
__device__ float g_ao[NTOK * DMODEL];    // attention output, [b,m,d]
__device__ float g_bias[M];              // log(exp(-d)+1e-12)
__device__ int   g_mask[NTOK];           // 1 = valid token, 0 = padded

// ---------------- mask dtype sniff + convert ----------------
// patch_mask is a bool array in the reference; the harness may hand it to us
// as uint8 (numpy bool), int32, or float32. Detect from the first 8192 bytes
// (always safely readable in all three cases) and convert to int.
__global__ void mask_convert(const unsigned int* __restrict__ w, int n) {
    __shared__ int not01, not0f;
    if (threadIdx.x == 0) { not01 = 0; not0f = 0; }
    __syncthreads();
    int b01 = 0, b0f = 0;
    for (int i = threadIdx.x; i < 2048; i += blockDim.x) {
        unsigned v = w[i];
        if (v > 1u) b01 = 1;
        if (v != 0u && v != 0x3F800000u) b0f = 1;
    }
    if (b01) atomicOr(&not01, 1);
    if (b0f) atomicOr(&not0f, 1);
    __syncthreads();
    int mode = (!not01) ? 1 : ((!not0f) ? 2 : 0); // 1=int32, 2=float32, 0=uint8
    for (int i = threadIdx.x; i < n; i += blockDim.x) {
        int v;
        if (mode == 1)      v = (((const int*)w)[i] != 0);
        else if (mode == 2) v = (((const float*)w)[i] != 0.0f);
        else                v = (((const unsigned char*)w)[i] != 0);
        g_mask[i] = v;
    }
}

__global__ void bias_init() {
    int i = blockIdx.x * blockDim.x + threadIdx.x;
    if (i < M) g_bias[i] = logf(expf(-(float)i) + 1e-12f); // DELTA/TAU == 1
}

// ---------------- QKV projection GEMM ----------------
// y[n,e] = sum_d X[n,d]*W[e,d] + b[e]; out written in [b,h,m,dh] layout.
// 64x64 C tile per block, 256 threads, 4x4 per thread, BK=16.
__global__ __launch_bounds__(256) void qkv_gemm(
    const float* __restrict__ X,
    const float* __restrict__ Wq, const float* __restrict__ bq,
    const float* __restrict__ Wk, const float* __restrict__ bk,
    const float* __restrict__ Wv, const float* __restrict__ bv)
{
    __shared__ float Xs[16][68];  // [k][n], padded for conflict-free LDS.128
    __shared__ float Ws[16][68];  // [k][e]
    const int z = blockIdx.z;
    const float* W    = (z == 0) ? Wq : (z == 1) ? Wk : Wv;
    const float* bias = (z == 0) ? bq : (z == 1) ? bk : bv;
    float* out        = (z == 0) ? g_q : (z == 1) ? g_k : g_v;

    const int t = threadIdx.x, ty = t >> 4, tx = t & 15;
    const int n0 = blockIdx.y << 6, e0 = blockIdx.x << 6;
    float acc[4][4] = {};

    for (int kk = 0; kk < DMODEL; kk += 16) {
        for (int i = t; i < 1024; i += 256) {
            int r = i >> 4, c = i & 15;
            Xs[c][r] = X[(size_t)(n0 + r) * DMODEL + kk + c];
            Ws[c][r] = W[(size_t)(e0 + r) * DMODEL + kk + c];
        }
        __syncthreads();
#pragma unroll
        for (int k = 0; k < 16; k++) {
            float4 af = *(const float4*)&Xs[k][ty << 2];
            float4 bf = *(const float4*)&Ws[k][tx << 2];
            float av[4] = {af.x, af.y, af.z, af.w};
            float bv4[4] = {bf.x, bf.y, bf.z, bf.w};
#pragma unroll
            for (int i = 0; i < 4; i++)
#pragma unroll
                for (int j = 0; j < 4; j++) acc[i][j] += av[i] * bv4[j];
        }
        __syncthreads();
    }
#pragma unroll
    for (int i = 0; i < 4; i++) {
        int n = n0 + (ty << 2) + i;
        int b = n >> 11, m = n & 2047;
#pragma unroll
        for (int j = 0; j < 4; j++) {
            int e = e0 + (tx << 2) + j;
            int hh = e >> 6, dh = e & 63;
            out[((((size_t)b << 3) + hh) * M + m) * DHEAD + dh] = acc[i][j] + bias[e];
        }
    }
}

// ---------------- flash attention (fp32) ----------------
// One block = one (b,h) and a 64-row query tile. Online softmax over 32 key tiles.
#define LDS 68
__global__ __launch_bounds__(256) void attn_kernel() {
    extern __shared__ float sm[];
    float* Qt = sm;                 // Qt[d*LDS + m]
    float* Kt = sm + 64 * LDS;      // Kt[d*LDS + n]
    float* Vs = sm + 2 * 64 * LDS;  // Vs[n*LDS + d]
    float* Ps = sm + 3 * 64 * LDS;  // Ps[n*LDS + m]
    __shared__ int msk[64];

    const int t = threadIdx.x, ty = t >> 4, tx = t & 15;
    const int bh = blockIdx.y, b = bh >> 3, hh = bh & 7;
    const int m0 = blockIdx.x << 6;
    const float* qb = g_q + (size_t)bh * M * DHEAD;
    const float* kb = g_k + (size_t)bh * M * DHEAD;
    const float* vb = g_v + (size_t)bh * M * DHEAD;

    for (int i = t; i < 4096; i += 256) {
        int r = i >> 6, c = i & 63;
        Qt[c * LDS + r] = qb[(size_t)(m0 + r) * DHEAD + c];
    }
    float acc[4][4], mrow[4], lrow[4];
#pragma unroll
    for (int i = 0; i < 4; i++) {
        mrow[i] = -3.0e38f; lrow[i] = 0.0f;
#pragma unroll
        for (int j = 0; j < 4; j++) acc[i][j] = 0.0f;
    }
    __syncthreads();

    for (int n0 = 0; n0 < M; n0 += 64) {
        for (int i = t; i < 4096; i += 256) {
            int r = i >> 6, c = i & 63;
            Kt[c * LDS + r] = kb[(size_t)(n0 + r) * DHEAD + c];
            Vs[r * LDS + c] = vb[(size_t)(n0 + r) * DHEAD + c];
        }
        if (t < 64) msk[t] = g_mask[b * M + n0 + t];
        __syncthreads();

        // S = Q K^T
        float s[4][4] = {};
#pragma unroll 8
        for (int d = 0; d < 64; d++) {
            float4 af = *(const float4*)&Qt[d * LDS + (ty << 2)];
            float4 bf = *(const float4*)&Kt[d * LDS + (tx << 2)];
            float av[4] = {af.x, af.y, af.z, af.w};
            float bv4[4] = {bf.x, bf.y, bf.z, bf.w};
#pragma unroll
            for (int i = 0; i < 4; i++)
#pragma unroll
                for (int j = 0; j < 4; j++) s[i][j] += av[i] * bv4[j];
        }
        // scale + bias + key mask
#pragma unroll
        for (int i = 0; i < 4; i++) {
            int mg = m0 + (ty << 2) + i;
#pragma unroll
            for (int j = 0; j < 4; j++) {
                int ng = n0 + (tx << 2) + j;
                int dd = mg - ng; dd = dd < 0 ? -dd : dd;
                float sc = s[i][j] * 0.125f + g_bias[dd];
                if (!msk[(tx << 2) + j]) sc = -1e9f;
                s[i][j] = sc;
            }
        }
        // online softmax update (row reductions across 16 tx lanes)
#pragma unroll
        for (int i = 0; i < 4; i++) {
            float mx = fmaxf(fmaxf(s[i][0], s[i][1]), fmaxf(s[i][2], s[i][3]));
#pragma unroll
            for (int o = 8; o > 0; o >>= 1)
                mx = fmaxf(mx, __shfl_xor_sync(0xffffffffu, mx, o, 32));
            float mnew = fmaxf(mrow[i], mx);
            float corr = __expf(mrow[i] - mnew);
            mrow[i] = mnew;
            float ps = 0.0f;
#pragma unroll
            for (int j = 0; j < 4; j++) {
                float p = __expf(s[i][j] - mnew);
                s[i][j] = p; ps += p;
            }
#pragma unroll
            for (int o = 8; o > 0; o >>= 1)
                ps += __shfl_xor_sync(0xffffffffu, ps, o, 32);
            lrow[i] = lrow[i] * corr + ps;
#pragma unroll
            for (int j = 0; j < 4; j++) acc[i][j] *= corr;
        }
        // write P transposed for the PV matmul
#pragma unroll
        for (int i = 0; i < 4; i++)
#pragma unroll
            for (int j = 0; j < 4; j++)
                Ps[((tx << 2) + j) * LDS + (ty << 2) + i] = s[i][j];
        __syncthreads();
        // O += P V
#pragma unroll 8
        for (int n = 0; n < 64; n++) {
            float4 af = *(const float4*)&Ps[n * LDS + (ty << 2)];
            float4 bf = *(const float4*)&Vs[n * LDS + (tx << 2)];
            float av[4] = {af.x, af.y, af.z, af.w};
            float bv4[4] = {bf.x, bf.y, bf.z, bf.w};
#pragma unroll
            for (int i = 0; i < 4; i++)
#pragma unroll
                for (int j = 0; j < 4; j++) acc[i][j] += av[i] * bv4[j];
        }
        __syncthreads();
    }
    // epilogue: normalize and write to [b,m,d] layout
    float* ob = g_ao + (size_t)b * M * DMODEL + (size_t)hh * DHEAD;
#pragma unroll
    for (int i = 0; i < 4; i++) {
        float inv = 1.0f / lrow[i];
        int m = m0 + (ty << 2) + i;
#pragma unroll
        for (int j = 0; j < 4; j++)
            ob[(size_t)m * DMODEL + (tx << 2) + j] = acc[i][j] * inv;
    }
}

// ---------------- output projection + mask ----------------
__global__ __launch_bounds__(256) void oproj_gemm(
    const float* __restrict__ Wo, const float* __restrict__ bo,
    float* __restrict__ out)
{
    __shared__ float Xs[16][68];
    __shared__ float Ws[16][68];
    const int t = threadIdx.x, ty = t >> 4, tx = t & 15;
    const int n0 = blockIdx.y << 6, e0 = blockIdx.x << 6;
    float acc[4][4] = {};

    for (int kk = 0; kk < DMODEL; kk += 16) {
        for (int i = t; i < 1024; i += 256) {
            int r = i >> 4, c = i & 15;
            Xs[c][r] = g_ao[(size_t)(n0 + r) * DMODEL + kk + c];
            Ws[c][r] = Wo[(size_t)(e0 + r) * DMODEL + kk + c];
        }
        __syncthreads();
#pragma unroll
        for (int k = 0; k < 16; k++) {
            float4 af = *(const float4*)&Xs[k][ty << 2];
            float4 bf = *(const float4*)&Ws[k][tx << 2];
            float av[4] = {af.x, af.y, af.z, af.w};
            float bv4[4] = {bf.x, bf.y, bf.z, bf.w};
#pragma unroll
            for (int i = 0; i < 4; i++)
#pragma unroll
                for (int j = 0; j < 4; j++) acc[i][j] += av[i] * bv4[j];
        }
        __syncthreads();
    }
#pragma unroll
    for (int i = 0; i < 4; i++) {
        int n = n0 + (ty << 2) + i;
        float mk = (float)g_mask[n];
#pragma unroll
        for (int j = 0; j < 4; j++) {
            int e = e0 + (tx << 2) + j;
            out[(size_t)n * DMODEL + e] = (acc[i][j] + bo[e]) * mk;
        }
    }
}

// ---------------- launch ----------------
extern "C" void kernel_launch(void* const* d_in, const int* in_sizes, int n_in,
                              void* d_out, int out_size) {
    const float* h  = (const float*)d_in[0];
    const void*  pm = d_in[1];
    const float* Wq = (const float*)d_in[2];
    const float* bq = (const float*)d_in[3];
    const float* Wk = (const float*)d_in[4];
    const float* bk = (const float*)d_in[5];
    const float* Wv = (const float*)d_in[6];
    const float* bv = (const float*)d_in[7];
    const float* Wo = (const float*)d_in[8];
    const float* bo = (const float*)d_in[9];
    float* out = (float*)d_out;

    mask_convert<<<1, 256>>>((const unsigned int*)pm, NTOK);
    bias_init<<<8, 256>>>();

    dim3 g1(DMODEL / 64, NTOK / 64, 3);
    qkv_gemm<<<g1, 256>>>(h, Wq, bq, Wk, bk, Wv, bv);

    const int att_smem = 4 * 64 * LDS * (int)sizeof(float); // 69632
    cudaFuncSetAttribute(attn_kernel, cudaFuncAttributeMaxDynamicSharedMemorySize, att_smem);
    dim3 g2(M / 64, BH);
    attn_kernel<<<g2, 256, att_smem>>>();

    dim3 g3(DMODEL / 64, NTOK / 64);
    oproj_gemm<<<g3, 256>>>(Wo, bo, out);
}

// round 2
// speedup vs baseline: 1.1337x; 1.1337x over previous
#include <cuda_runtime.h>
#include <math.h>

#define B 4
#define M 2048
#define DMODEL 512
#define NHEAD 8
#define DHEAD 64
#define NTOK (B*M)          // 8192
#define BH (B*NHEAD)        // 32

// ---------------- scratch (device globals) ----------------
__device__ float g_q[BH * M * DHEAD];    // [b,h,m,dh], pre-scaled by 1/8
__device__ float g_k[BH * M * DHEAD];
__device__ float g_v[BH * M * DHEAD];
__device__ float g_ao[NTOK * DMODEL];    // attention output, [b,m,d]
__device__ float g_bias[M];              // log(exp(-d)+1e-12)
__device__ int   g_mask[NTOK];

// ---------------- mask dtype sniff + convert ----------------
__global__ void mask_convert(const unsigned int* __restrict__ w, int n) {
    __shared__ int not01, not0f;
    if (threadIdx.x == 0) { not01 = 0; not0f = 0; }
    __syncthreads();
    int b01 = 0, b0f = 0;
    for (int i = threadIdx.x; i < 2048; i += blockDim.x) {
        unsigned v = w[i];
        if (v > 1u) b01 = 1;
        if (v != 0u && v != 0x3F800000u) b0f = 1;
    }
    if (b01) atomicOr(&not01, 1);
    if (b0f) atomicOr(&not0f, 1);
    __syncthreads();
    int mode = (!not01) ? 1 : ((!not0f) ? 2 : 0); // 1=int32, 2=float32, 0=uint8
    for (int i = threadIdx.x; i < n; i += blockDim.x) {
        int v;
        if (mode == 1)      v = (((const int*)w)[i] != 0);
        else if (mode == 2) v = (((const float*)w)[i] != 0.0f);
        else                v = (((const unsigned char*)w)[i] != 0);
        g_mask[i] = v;
    }
}

__global__ void bias_init() {
    int i = blockIdx.x * blockDim.x + threadIdx.x;
    if (i < M) g_bias[i] = logf(expf(-(float)i) + 1e-12f);
}

// ---------------- QKV projection GEMM: 128x128 tile, 8x8/thread ----------------
__global__ __launch_bounds__(256) void qkv_gemm(
    const float* __restrict__ X,
    const float* __restrict__ Wq, const float* __restrict__ bq,
    const float* __restrict__ Wk, const float* __restrict__ bk,
    const float* __restrict__ Wv, const float* __restrict__ bv)
{
    __shared__ float Xs[16][132];
    __shared__ float Ws[16][132];
    const int z = blockIdx.z;
    const float* W    = (z == 0) ? Wq : (z == 1) ? Wk : Wv;
    const float* bias = (z == 0) ? bq : (z == 1) ? bk : bv;
    float* out        = (z == 0) ? g_q : (z == 1) ? g_k : g_v;
    const float oscale = (z == 0) ? 0.125f : 1.0f;   // fold 1/sqrt(dh) into Q

    const int t = threadIdx.x, ty = t >> 4, tx = t & 15;
    const int n0 = blockIdx.y << 7, e0 = blockIdx.x << 7;
    float acc[8][8] = {};

    for (int kk = 0; kk < DMODEL; kk += 16) {
        for (int i = t; i < 2048; i += 256) {
            int r = i >> 4, c = i & 15;
            Xs[c][r] = X[(size_t)(n0 + r) * DMODEL + kk + c];
            Ws[c][r] = W[(size_t)(e0 + r) * DMODEL + kk + c];
        }
        __syncthreads();
#pragma unroll 8
        for (int k = 0; k < 16; k++) {
            float4 a0 = *(const float4*)&Xs[k][ty << 3];
            float4 a1 = *(const float4*)&Xs[k][(ty << 3) + 4];
            float4 b0 = *(const float4*)&Ws[k][tx << 3];
            float4 b1 = *(const float4*)&Ws[k][(tx << 3) + 4];
            float av[8] = {a0.x, a0.y, a0.z, a0.w, a1.x, a1.y, a1.z, a1.w};
            float bv8[8] = {b0.x, b0.y, b0.z, b0.w, b1.x, b1.y, b1.z, b1.w};
#pragma unroll
            for (int i = 0; i < 8; i++)
#pragma unroll
                for (int j = 0; j < 8; j++) acc[i][j] += av[i] * bv8[j];
        }
        __syncthreads();
    }
#pragma unroll
    for (int i = 0; i < 8; i++) {
        int n = n0 + (ty << 3) + i;
        int b = n >> 11, m = n & 2047;
        int e_base = e0 + (tx << 3);
        int hh = e_base >> 6, dh0 = e_base & 63;
        float* op = out + ((((size_t)b << 3) + hh) * M + m) * DHEAD + dh0;
        float4 r0, r1;
        r0.x = (acc[i][0] + bias[e_base + 0]) * oscale;
        r0.y = (acc[i][1] + bias[e_base + 1]) * oscale;
        r0.z = (acc[i][2] + bias[e_base + 2]) * oscale;
        r0.w = (acc[i][3] + bias[e_base + 3]) * oscale;
        r1.x = (acc[i][4] + bias[e_base + 4]) * oscale;
        r1.y = (acc[i][5] + bias[e_base + 5]) * oscale;
        r1.z = (acc[i][6] + bias[e_base + 6]) * oscale;
        r1.w = (acc[i][7] + bias[e_base + 7]) * oscale;
        *(float4*)op = r0;
        *(float4*)(op + 4) = r1;
    }
}

// ---------------- flash attention fp32: 128-row Q tile, 8x8/thread ----------------
// smem: Qt[64][132] (d-major), Kt[64][68] (d-major), Vs[64][68], Ps[64][128] (XOR-swizzled P^T)
#define ATT_SMEM ((64*132 + 64*68 + 64*68 + 64*128) * 4)
__global__ __launch_bounds__(128) void attn_kernel() {
    extern __shared__ float sm[];
    float* Qt = sm;
    float* Kt = Qt + 64 * 132;
    float* Vs = Kt + 64 * 68;
    float* Ps = Vs + 64 * 68;
    __shared__ int   msk[64];
    __shared__ float sbias[192];

    const int t = threadIdx.x;
    const int tx = t & 7, ty = t >> 3;   // tx: 8 col-groups, ty: 16 row-groups
    const int bh = blockIdx.y, b = bh >> 3, hh = bh & 7;
    const int m0 = blockIdx.x << 7;
    const float* qb = g_q + (size_t)bh * M * DHEAD;
    const float* kb = g_k + (size_t)bh * M * DHEAD;
    const float* vb = g_v + (size_t)bh * M * DHEAD;

    for (int i = t; i < 8192; i += 128) {
        int r = i >> 6, c = i & 63;
        Qt[c * 132 + r] = qb[(size_t)(m0 + r) * DHEAD + c];
    }
    float acc[8][8] = {};
    float mrow[8], lrow[8];
#pragma unroll
    for (int i = 0; i < 8; i++) { mrow[i] = -3.0e38f; lrow[i] = 0.0f; }
    __syncthreads();

    for (int n0 = 0; n0 < M; n0 += 64) {
        for (int i = t; i < 4096; i += 128) {
            int r = i >> 6, c = i & 63;
            Kt[c * 68 + r] = kb[(size_t)(n0 + r) * DHEAD + c];
            Vs[r * 68 + c] = vb[(size_t)(n0 + r) * DHEAD + c];
        }
        if (t < 64) msk[t] = g_mask[b * M + n0 + t];
        // bias window: delta = m-n in [m0-n0-63, m0-n0+127]
        for (int i = t; i < 191; i += 128) {
            int d = m0 - n0 + i - 63;
            sbias[i] = g_bias[d < 0 ? -d : d];
        }
        __syncthreads();

        // S = Q K^T  (Q pre-scaled)
        float s[8][8] = {};
#pragma unroll 4
        for (int d = 0; d < 64; d++) {
            float4 q0 = *(const float4*)&Qt[d * 132 + (ty << 3)];
            float4 q1 = *(const float4*)&Qt[d * 132 + (ty << 3) + 4];
            float4 k0 = *(const float4*)&Kt[d * 68 + (tx << 3)];
            float4 k1 = *(const float4*)&Kt[d * 68 + (tx << 3) + 4];
            float qv[8] = {q0.x, q0.y, q0.z, q0.w, q1.x, q1.y, q1.z, q1.w};
            float kv[8] = {k0.x, k0.y, k0.z, k0.w, k1.x, k1.y, k1.z, k1.w};
#pragma unroll
            for (int i = 0; i < 8; i++)
#pragma unroll
                for (int j = 0; j < 8; j++) s[i][j] += qv[i] * kv[j];
        }
        // bias + mask + online softmax
#pragma unroll
        for (int i = 0; i < 8; i++) {
            int li = (ty << 3) + i;
#pragma unroll
            for (int j = 0; j < 8; j++) {
                int lj = (tx << 3) + j;
                float sc = s[i][j] + sbias[li - lj + 63];
                s[i][j] = msk[lj] ? sc : -1e9f;
            }
            float mx = s[i][0];
#pragma unroll
            for (int j = 1; j < 8; j++) mx = fmaxf(mx, s[i][j]);
            mx = fmaxf(mx, __shfl_xor_sync(0xffffffffu, mx, 4));
            mx = fmaxf(mx, __shfl_xor_sync(0xffffffffu, mx, 2));
            mx = fmaxf(mx, __shfl_xor_sync(0xffffffffu, mx, 1));
            float mnew = fmaxf(mrow[i], mx);
            float corr = __expf(mrow[i] - mnew);
            mrow[i] = mnew;
            float ps = 0.0f;
#pragma unroll
            for (int j = 0; j < 8; j++) {
                float p = __expf(s[i][j] - mnew);
                s[i][j] = p; ps += p;
            }
            ps += __shfl_xor_sync(0xffffffffu, ps, 4);
            ps += __shfl_xor_sync(0xffffffffu, ps, 2);
            ps += __shfl_xor_sync(0xffffffffu, ps, 1);
            lrow[i] = lrow[i] * corr + ps;
#pragma unroll
            for (int j = 0; j < 8; j++) acc[i][j] *= corr;
        }
        // write P^T[n][m], XOR-swizzled at float4 granularity: col4' = col4 ^ (row>>3)
#pragma unroll
        for (int j = 0; j < 8; j++) {
            int row = (tx << 3) + j;   // row>>3 == tx
            float4 v0 = make_float4(s[0][j], s[1][j], s[2][j], s[3][j]);
            float4 v1 = make_float4(s[4][j], s[5][j], s[6][j], s[7][j]);
            *(float4*)&Ps[row * 128 + ((((ty << 1) + 0) ^ tx) << 2)] = v0;
            *(float4*)&Ps[row * 128 + ((((ty << 1) + 1) ^ tx) << 2)] = v1;
        }
        __syncthreads();
        // O += P V
#pragma unroll 4
        for (int n = 0; n < 64; n++) {
            int c = n >> 3;
            float4 p0 = *(const float4*)&Ps[n * 128 + ((((ty << 1) + 0) ^ c) << 2)];
            float4 p1 = *(const float4*)&Ps[n * 128 + ((((ty << 1) + 1) ^ c) << 2)];
            float4 v0 = *(const float4*)&Vs[n * 68 + (tx << 3)];
            float4 v1 = *(const float4*)&Vs[n * 68 + (tx << 3) + 4];
            float pv[8] = {p0.x, p0.y, p0.z, p0.w, p1.x, p1.y, p1.z, p1.w};
            float vv[8] = {v0.x, v0.y, v0.z, v0.w, v1.x, v1.y, v1.z, v1.w};
#pragma unroll
            for (int i = 0; i < 8; i++)
#pragma unroll
                for (int j = 0; j < 8; j++) acc[i][j] += pv[i] * vv[j];
        }
        __syncthreads();
    }
    // epilogue
    float* ob = g_ao + (size_t)b * M * DMODEL + (size_t)hh * DHEAD + (tx << 3);
#pragma unroll
    for (int i = 0; i < 8; i++) {
        float inv = 1.0f / lrow[i];
        int m = m0 + (ty << 3) + i;
        float4 r0 = make_float4(acc[i][0]*inv, acc[i][1]*inv, acc[i][2]*inv, acc[i][3]*inv);
        float4 r1 = make_float4(acc[i][4]*inv, acc[i][5]*inv, acc[i][6]*inv, acc[i][7]*inv);
        *(float4*)&ob[(size_t)m * DMODEL] = r0;
        *(float4*)&ob[(size_t)m * DMODEL + 4] = r1;
    }
}

// ---------------- output projection + mask: 128x128 tile ----------------
__global__ __launch_bounds__(256) void oproj_gemm(
    const float* __restrict__ Wo, const float* __restrict__ bo,
    float* __restrict__ out)
{
    __shared__ float Xs[16][132];
    __shared__ float Ws[16][132];
    const int t = threadIdx.x, ty = t >> 4, tx = t & 15;
    const int n0 = blockIdx.y << 7, e0 = blockIdx.x << 7;
    float acc[8][8] = {};

    for (int kk = 0; kk < DMODEL; kk += 16) {
        for (int i = t; i < 2048; i += 256) {
            int r = i >> 4, c = i & 15;
            Xs[c][r] = g_ao[(size_t)(n0 + r) * DMODEL + kk + c];
            Ws[c][r] = Wo[(size_t)(e0 + r) * DMODEL + kk + c];
        }
        __syncthreads();
#pragma unroll 8
        for (int k = 0; k < 16; k++) {
            float4 a0 = *(const float4*)&Xs[k][ty << 3];
            float4 a1 = *(const float4*)&Xs[k][(ty << 3) + 4];
            float4 b0 = *(const float4*)&Ws[k][tx << 3];
            float4 b1 = *(const float4*)&Ws[k][(tx << 3) + 4];
            float av[8] = {a0.x, a0.y, a0.z, a0.w, a1.x, a1.y, a1.z, a1.w};
            float bv8[8] = {b0.x, b0.y, b0.z, b0.w, b1.x, b1.y, b1.z, b1.w};
#pragma unroll
            for (int i = 0; i < 8; i++)
#pragma unroll
                for (int j = 0; j < 8; j++) acc[i][j] += av[i] * bv8[j];
        }
        __syncthreads();
    }
#pragma unroll
    for (int i = 0; i < 8; i++) {
        int n = n0 + (ty << 3) + i;
        float mk = (float)g_mask[n];
        int e = e0 + (tx << 3);
        float4 r0, r1;
        r0.x = (acc[i][0] + bo[e+0]) * mk; r0.y = (acc[i][1] + bo[e+1]) * mk;
        r0.z = (acc[i][2] + bo[e+2]) * mk; r0.w = (acc[i][3] + bo[e+3]) * mk;
        r1.x = (acc[i][4] + bo[e+4]) * mk; r1.y = (acc[i][5] + bo[e+5]) * mk;
        r1.z = (acc[i][6] + bo[e+6]) * mk; r1.w = (acc[i][7] + bo[e+7]) * mk;
        *(float4*)&out[(size_t)n * DMODEL + e] = r0;
        *(float4*)&out[(size_t)n * DMODEL + e + 4] = r1;
    }
}

// ---------------- launch ----------------
extern "C" void kernel_launch(void* const* d_in, const int* in_sizes, int n_in,
                              void* d_out, int out_size) {
    const float* h  = (const float*)d_in[0];
    const void*  pm = d_in[1];
    const float* Wq = (const float*)d_in[2];
    const float* bq = (const float*)d_in[3];
    const float* Wk = (const float*)d_in[4];
    const float* bk = (const float*)d_in[5];
    const float* Wv = (const float*)d_in[6];
    const float* bv = (const float*)d_in[7];
    const float* Wo = (const float*)d_in[8];
    const float* bo = (const float*)d_in[9];
    float* out = (float*)d_out;

    mask_convert<<<1, 256>>>((const unsigned int*)pm, NTOK);
    bias_init<<<8, 256>>>();

    dim3 g1(DMODEL / 128, NTOK / 128, 3);
    qkv_gemm<<<g1, 256>>>(h, Wq, bq, Wk, bk, Wv, bv);

    cudaFuncSetAttribute(attn_kernel, cudaFuncAttributeMaxDynamicSharedMemorySize, ATT_SMEM);
    dim3 g2(M / 128, BH);
    attn_kernel<<<g2, 128, ATT_SMEM>>>();

    dim3 g3(DMODEL / 128, NTOK / 128);
    oproj_gemm<<<g3, 256>>>(Wo, bo, out);
}